// round 15
// baseline (speedup 1.0000x reference)
#include <cuda_runtime.h>
#include <cuda_fp16.h>
#include <math.h>
#include <stdint.h>

#define B_SZ    4
#define S_LEN   4096
#define D_MODEL 1024
#define HEAD    64
#define R_TOT   (B_SZ * S_LEN)
#define HALF    (HEAD / 2)
#define LOG2E   1.4426950408889634f
#define SPLIT   4
#define NK16    (D_MODEL / 16)   // 64 k16-slices

// Scratch (allocation-free rule: __device__ globals)
// g_Qh: fp16 rope(Q)*0.125; g_Kh: fp16 rope(K) [row][col];
// g_Vh2: fp16 V transposed kv-pair packed: [batch][d][spair] half2.
__device__ __half  g_Qh[R_TOT * HEAD];
__device__ __half  g_Kh[R_TOT * HEAD];
__device__ __half2 g_Vh2[R_TOT * HEAD / 2];
__device__ float g_sin[S_LEN * HALF];
__device__ float g_cos[S_LEN * HALF];
__device__ float g_theta[HALF];
__device__ float g_Os[(size_t)SPLIT * R_TOT * HEAD];
__device__ float g_m[SPLIT * R_TOT];
__device__ float g_l[SPLIT * R_TOT];
// Precomputed W B-fragments (fp16, m16n8k16): [which][k16][nc][lane] = {b0, b1}
__device__ uint2 g_Wfh[3][NK16][8][32];

// ---------------------------------------------------------------------------
__device__ __forceinline__ void mma_f16(float c[4], const unsigned a[4],
                                        unsigned b0, unsigned b1) {
    asm volatile(
        "mma.sync.aligned.m16n8k16.row.col.f32.f16.f16.f32 "
        "{%0,%1,%2,%3}, {%4,%5,%6,%7}, {%8,%9}, {%0,%1,%2,%3};\n"
        : "+f"(c[0]), "+f"(c[1]), "+f"(c[2]), "+f"(c[3])
        : "r"(a[0]), "r"(a[1]), "r"(a[2]), "r"(a[3]), "r"(b0), "r"(b1));
}

__device__ __forceinline__ unsigned pack_h2(float a, float b) {
    __half2 h = __floats2half2_rn(a, b);
    return *(unsigned*)&h;
}

__device__ __forceinline__ uint32_t smem_u32(const void* p) {
    uint32_t a;
    asm("{ .reg .u64 t; cvta.to.shared.u64 t, %1; cvt.u32.u64 %0, t; }"
        : "=r"(a) : "l"(p));
    return a;
}

__device__ __forceinline__ void cp16(uint32_t dst, const void* src) {
    asm volatile("cp.async.cg.shared.global [%0], [%1], 16;"
                 :: "r"(dst), "l"(src) : "memory");
}
#define CP_COMMIT()  asm volatile("cp.async.commit_group;" ::: "memory")
#define CP_WAIT(n)   asm volatile("cp.async.wait_group %0;" :: "n"(n) : "memory")

// ---------------------------------------------------------------------------
__global__ void theta_kernel() {
    int i = threadIdx.x;
    if (i < HALF) g_theta[i] = (float)pow(10000.0, -(double)i / (double)HALF);
}

// RoPE table: freq = fp32(s * theta_fp32); accurate sin/cos via double range
// reduction + fp32 Taylor on |r|<=pi/4.
__global__ void rope_table_kernel() {
    int idx = blockIdx.x * blockDim.x + threadIdx.x;
    if (idx >= S_LEN * HALF) return;
    int s = idx >> 5;
    int i = idx & (HALF - 1);
    float fr = (float)s * g_theta[i];

    double x  = (double)fr;
    double kd = rint(x * 0.6366197723675814);
    int    k  = (int)kd;
    double r  = fma(-kd, 1.5707963267948966, x);
    r         = fma(-kd, 6.123233995736766e-17, r);
    float rf = (float)r;
    float r2 = rf * rf;
    float sp = rf * (1.f + r2 * (-1.66666667e-1f + r2 * (8.33333310e-3f +
               r2 * (-1.98412698e-4f + r2 * 2.75573140e-6f))));
    float cp = 1.f + r2 * (-0.5f + r2 * (4.16666679e-2f +
               r2 * (-1.38888892e-3f + r2 * 2.47868524e-5f)));
    float sn, cs;
    switch (k & 3) {
        case 0:  sn = sp;  cs = cp;  break;
        case 1:  sn = cp;  cs = -sp; break;
        case 2:  sn = -sp; cs = -cp; break;
        default: sn = -cp; cs = sp;  break;
    }
    g_sin[idx] = sn;
    g_cos[idx] = cs;
}

// ---------------------------------------------------------------------------
// Precompute W B-fragments (fp16) for m16n8k16 projection MMAs.
// ---------------------------------------------------------------------------
__global__ void wfrag_kernel(const float* __restrict__ Wq,
                             const float* __restrict__ Wk,
                             const float* __restrict__ Wv) {
    int tid = blockIdx.x * 256 + threadIdx.x;
    if (tid >= 3 * NK16 * 8 * 32) return;
    int lane  = tid & 31;
    int nc    = (tid >> 5) & 7;
    int ks    = (tid >> 8) & (NK16 - 1);
    int which = tid >> 14;
    const float* W = (which == 0) ? Wq : (which == 1) ? Wk : Wv;
    int g = lane >> 2, t = lane & 3;
    int n = nc * 8 + g;
    int k0 = ks * 16 + 2 * t;
    uint2 v;
    v.x = pack_h2(W[(size_t)(k0    ) * HEAD + n], W[(size_t)(k0 + 1) * HEAD + n]);
    v.y = pack_h2(W[(size_t)(k0 + 8) * HEAD + n], W[(size_t)(k0 + 9) * HEAD + n]);
    g_Wfh[which][ks][nc][lane] = v;
}

// ---------------------------------------------------------------------------
// FUSED QKV projection v2, fp16 m16n8k16, fp32 accum, + RoPE.
// CTA = 64 rows x 64 cols, 256 threads = 8 warps: warp tile 16 rows x 32 cols
// (rowgrp = warp>>1, colgrp = warp&1). Accums 3x4x4 = 48 regs/thread ->
// 2 CTAs/SM (16 warps). A-fragments loaded DIRECTLY from gmem; only shared W
// slices staged in double-buffered smem via cp.async.
// ---------------------------------------------------------------------------
#define WFH_BYTES  (4 * 8 * 32 * 8)                  // 8192 per which per chunk
#define WQH_STRIDE (NK16 * 8 * 32 * 8)               // 131072 bytes per which
#define PBUF       (3 * WFH_BYTES)                   // 24576
#define PSMEM      (2 * PBUF)                        // 49152

__global__ void __launch_bounds__(256, 2) proj_fused_kernel(const float* __restrict__ x) {
    extern __shared__ char psm[];

    const int tid    = threadIdx.x;
    const int warp   = tid >> 5;
    const int lane   = tid & 31;
    const int g      = lane >> 2;
    const int t      = lane & 3;
    const int rowgrp = warp >> 1;
    const int colgrp = warp & 1;
    const int row0   = blockIdx.x * 64;
    const int r0     = rowgrp * 16 + g;      // local rows r0, r0+8 (0..63)

    const uint32_t smb = smem_u32(psm);

    // --- stage W slices for chunk c into buffer b (6 cp16 per thread) ---
    auto stage = [&](int c, int b) {
        const uint32_t base = smb + b * PBUF;
        const char* ws = (const char*)&g_Wfh[0][0][0][0] + (size_t)c * WFH_BYTES;
        #pragma unroll
        for (int wq = 0; wq < 3; wq++) {
            #pragma unroll
            for (int j = 0; j < 2; j++) {
                int idx = j * 256 + tid;
                cp16(base + wq * WFH_BYTES + idx * 16,
                     ws + (size_t)wq * WQH_STRIDE + idx * 16);
            }
        }
        CP_COMMIT();
    };

    float cacc[3][4][4] = {};
    const float* xr0 = x + (size_t)(row0 + r0) * D_MODEL;
    const float* xr1 = x + (size_t)(row0 + r0 + 8) * D_MODEL;

    stage(0, 0);
    for (int c = 0; c < 16; c++) {
        const int bufsel = c & 1;
        if (c < 15) { stage(c + 1, bufsel ^ 1); CP_WAIT(1); }
        else        { CP_WAIT(0); }
        __syncthreads();

        const char* bufp = psm + bufsel * PBUF;

        #pragma unroll
        for (int ks = 0; ks < 4; ks++) {
            const int cb = c * 64 + ks * 16 + 2 * t;
            float2 f0 = *(const float2*)(xr0 + cb);
            float2 f1 = *(const float2*)(xr1 + cb);
            float2 f2 = *(const float2*)(xr0 + cb + 8);
            float2 f3 = *(const float2*)(xr1 + cb + 8);
            unsigned a[4];
            a[0] = pack_h2(f0.x, f0.y);
            a[1] = pack_h2(f1.x, f1.y);
            a[2] = pack_h2(f2.x, f2.y);
            a[3] = pack_h2(f3.x, f3.y);

            #pragma unroll
            for (int wq = 0; wq < 3; wq++) {
                const uint2* wrow = (const uint2*)(bufp + wq * WFH_BYTES) +
                                    ks * 256 + colgrp * 128 + lane;
                #pragma unroll
                for (int nc = 0; nc < 4; nc++) {
                    uint2 b = wrow[nc * 32];
                    mma_f16(cacc[wq][nc], a, b.x, b.y);
                }
            }
        }
        __syncthreads();
    }

    // Epilogue: RoPE; Q/K -> fp16 direct; V -> smem transpose (pairs along kv)
    const int gr0 = row0 + r0;
    const int s0  = gr0 & (S_LEN - 1);
    const int s1  = (gr0 + 8) & (S_LEN - 1);
    __half* Vt = (__half*)psm;                      // [64 d][72 halfs]
    #pragma unroll
    for (int wq = 0; wq < 3; wq++) {
        float (*cc)[4] = cacc[wq];
        #pragma unroll
        for (int nc = 0; nc < 4; nc++) {
            int col = colgrp * 32 + nc * 8 + 2 * t;
            float v0 = cc[nc][0], v1 = cc[nc][1], v2 = cc[nc][2], v3 = cc[nc][3];
            if (wq < 2) {
                int i0 = col >> 1;
                float sn0 = g_sin[s0 * HALF + i0], cs0 = g_cos[s0 * HALF + i0];
                float sn1 = g_sin[s1 * HALF + i0], cs1 = g_cos[s1 * HALF + i0];
                float a0 = v0 * cs0 - v1 * sn0, b0 = v1 * cs0 + v0 * sn0;
                float a1 = v2 * cs1 - v3 * sn1, b1 = v3 * cs1 + v2 * sn1;
                if (wq == 0) { a0 *= 0.125f; b0 *= 0.125f; a1 *= 0.125f; b1 *= 0.125f; }
                __half* outp = (wq == 0) ? g_Qh : g_Kh;
                *(__half2*)(outp + (size_t)gr0 * HEAD + col)       = __floats2half2_rn(a0, b0);
                *(__half2*)(outp + (size_t)(gr0 + 8) * HEAD + col) = __floats2half2_rn(a1, b1);
            } else {
                Vt[(col    ) * 72 + r0]     = __float2half_rn(v0);
                Vt[(col + 1) * 72 + r0]     = __float2half_rn(v1);
                Vt[(col    ) * 72 + r0 + 8] = __float2half_rn(v2);
                Vt[(col + 1) * 72 + r0 + 8] = __float2half_rn(v3);
            }
        }
    }
    __syncthreads();
    // Cooperative coalesced write of transposed V: 64 d-rows x 64 halfs
    // (= 32 spairs = 128 B = 8 uint4 per d-row; 512 uint4 total)
    {
        const int batch  = row0 >> 12;
        const int spair0 = (row0 & (S_LEN - 1)) >> 1;
        #pragma unroll
        for (int j = 0; j < 2; j++) {
            int idx = j * 256 + tid;
            int d   = idx >> 3;        // 0..63
            int c8  = idx & 7;         // 8 x 16B per 128-byte d-row
            uint4 v = *(uint4*)(psm + d * 144 + c8 * 16);
            *(uint4*)&g_Vh2[(size_t)(batch * HEAD + d) * (S_LEN / 2) + spair0 + c8 * 4] = v;
        }
    }
}

// ---------------------------------------------------------------------------
// fp16 flash attention: m16n8k16 QK and PV, 32 q-rows/warp, 128 q-rows/block,
// 4-way split-KV, cp.async double-buffered. PV A-fragments come straight from
// softmax C-fragments (pair layouts match) — no shuffles.
// ---------------------------------------------------------------------------
#define KT_STRIDE 72                     // halfs per K row
#define KT_BYTES  (64 * KT_STRIDE * 2)   // 9216
#define VT_STRIDE 36                     // half2 per V d-row (d-major)
#define VT_BYTES  (64 * VT_STRIDE * 4)   // 9216
#define KV_BUF2   (KT_BYTES + VT_BYTES)  // 18432
#define ATTN_SMEM (2 * KV_BUF2)          // 36864

__global__ void __launch_bounds__(128, 2) attn_mma_kernel() {
    extern __shared__ char asmem[];

    const int tid   = threadIdx.x;
    const int warp  = tid >> 5;
    const int lane  = tid & 31;
    const int g     = lane >> 2;
    const int t     = lane & 3;
    const int idx   = blockIdx.x;
    const int qt    = 31 - (idx >> 4);
    const int rem   = idx & 15;
    const int batch = rem >> 2;
    const int split = rem & 3;
    const int q0    = qt * 128;
    const int n     = 2 * qt + 2;
    const int lo    = (split * n) >> 2;
    const int hi    = ((split + 1) * n) >> 2;

    const int    rl0     = warp * 32 + g;
    const size_t rowbase = (size_t)batch * S_LEN + q0;

    if (lo == hi) {
        if (t == 0) {
            int pb = split * R_TOT;
            #pragma unroll
            for (int rg = 0; rg < 4; rg++) {
                g_m[pb + rowbase + rl0 + rg * 8] = -1e30f;
                g_l[pb + rowbase + rl0 + rg * 8] = 0.f;
            }
        }
        return;
    }

    const uint32_t smb = smem_u32(asmem);

    // Q tile (128 rows fp16) -> smem [r][72] -> A-frags (pairs along d)
    unsigned qa[2][4][4];
    {
        const __half* Qg = g_Qh + rowbase * HEAD;
        #pragma unroll
        for (int j = 0; j < 8; j++) {
            int i = j * 128 + tid;
            int r = i >> 3, c8 = i & 7;
            cp16(smb + r * (KT_STRIDE * 2) + c8 * 16, Qg + (size_t)r * HEAD + c8 * 8);
        }
        CP_COMMIT(); CP_WAIT(0);
        __syncthreads();
        const __half* Qs = (const __half*)asmem;
        #pragma unroll
        for (int tt = 0; tt < 2; tt++) {
            const int r0 = rl0 + tt * 16;
            #pragma unroll
            for (int kc = 0; kc < 4; kc++) {
                qa[tt][kc][0] = *(const unsigned*)&Qs[ r0      * KT_STRIDE + kc * 16 + 2 * t];
                qa[tt][kc][1] = *(const unsigned*)&Qs[(r0 + 8) * KT_STRIDE + kc * 16 + 2 * t];
                qa[tt][kc][2] = *(const unsigned*)&Qs[ r0      * KT_STRIDE + kc * 16 + 2 * t + 8];
                qa[tt][kc][3] = *(const unsigned*)&Qs[(r0 + 8) * KT_STRIDE + kc * 16 + 2 * t + 8];
            }
        }
        __syncthreads();
    }

    float o0[8][4], o1[8][4];
    #pragma unroll
    for (int nc = 0; nc < 8; nc++) {
        o0[nc][0] = o0[nc][1] = o0[nc][2] = o0[nc][3] = 0.f;
        o1[nc][0] = o1[nc][1] = o1[nc][2] = o1[nc][3] = 0.f;
    }
    float m[4] = {-1e30f, -1e30f, -1e30f, -1e30f};
    float l[4] = {0.f, 0.f, 0.f, 0.f};

    auto stageKV = [&](int jt, int b) {
        const uint32_t kb = smb + b * KV_BUF2;
        const __half*  Kg = g_Kh + ((size_t)batch * S_LEN + jt * 64) * HEAD;
        const __half2* Vg = g_Vh2 + (size_t)batch * HEAD * (S_LEN / 2) + jt * 32;
        #pragma unroll
        for (int j = 0; j < 4; j++) {
            int i = j * 128 + tid;
            int r = i >> 3, c8 = i & 7;
            cp16(kb + r * (KT_STRIDE * 2) + c8 * 16, Kg + (size_t)r * HEAD + c8 * 8);
        }
        // V tile: 64 d-rows x 32 half2 (128 B) = 512 cp16
        #pragma unroll
        for (int j = 0; j < 4; j++) {
            int i = j * 128 + tid;
            int d = i >> 3, c16 = i & 7;
            cp16(kb + KT_BYTES + d * (VT_STRIDE * 4) + c16 * 16,
                 Vg + (size_t)d * (S_LEN / 2) + c16 * 4);
        }
        CP_COMMIT();
    };

    stageKV(lo, 0);
    for (int jt = lo; jt < hi; jt++) {
        const int buf = (jt - lo) & 1;
        if (jt + 1 < hi) { stageKV(jt + 1, buf ^ 1); CP_WAIT(1); }
        else             { CP_WAIT(0); }
        __syncthreads();

        const __half*   Ksb = (const __half*)(asmem + buf * KV_BUF2);
        const unsigned* Vsb = (const unsigned*)(asmem + buf * KV_BUF2 + KT_BYTES);

        // S = Q K^T (fp16, k16) — both A-tiles share each B-fragment
        float s0[8][4], s1[8][4];
        #pragma unroll
        for (int nc = 0; nc < 8; nc++) {
            s0[nc][0] = s0[nc][1] = s0[nc][2] = s0[nc][3] = 0.f;
            s1[nc][0] = s1[nc][1] = s1[nc][2] = s1[nc][3] = 0.f;
            const __half* Krow = Ksb + (nc * 8 + g) * KT_STRIDE;
            #pragma unroll
            for (int kc = 0; kc < 4; kc++) {
                unsigned b0 = *(const unsigned*)&Krow[kc * 16 + 2 * t];
                unsigned b1 = *(const unsigned*)&Krow[kc * 16 + 2 * t + 8];
                mma_f16(s0[nc], qa[0][kc], b0, b1);
                mma_f16(s1[nc], qa[1][kc], b0, b1);
            }
        }

        // Causal mask (last two kv tiles of the 128-row q-tile)
        if (jt >= 2 * qt) {
            const int base = q0 - jt * 64;
            #pragma unroll
            for (int nc = 0; nc < 8; nc++) {
                int cl = nc * 8 + 2 * t;
                int L0 = base + rl0, L1 = L0 + 8, L2 = L0 + 16, L3 = L0 + 24;
                if (cl     > L0) s0[nc][0] = -1e30f;
                if (cl + 1 > L0) s0[nc][1] = -1e30f;
                if (cl     > L1) s0[nc][2] = -1e30f;
                if (cl + 1 > L1) s0[nc][3] = -1e30f;
                if (cl     > L2) s1[nc][0] = -1e30f;
                if (cl + 1 > L2) s1[nc][1] = -1e30f;
                if (cl     > L3) s1[nc][2] = -1e30f;
                if (cl + 1 > L3) s1[nc][3] = -1e30f;
            }
        }

        // Row max per group
        float mt[4] = {-1e30f, -1e30f, -1e30f, -1e30f};
        #pragma unroll
        for (int nc = 0; nc < 8; nc++) {
            mt[0] = fmaxf(mt[0], fmaxf(s0[nc][0], s0[nc][1]));
            mt[1] = fmaxf(mt[1], fmaxf(s0[nc][2], s0[nc][3]));
            mt[2] = fmaxf(mt[2], fmaxf(s1[nc][0], s1[nc][1]));
            mt[3] = fmaxf(mt[3], fmaxf(s1[nc][2], s1[nc][3]));
        }
        #pragma unroll
        for (int rg = 0; rg < 4; rg++) {
            mt[rg] = fmaxf(mt[rg], __shfl_xor_sync(0xffffffffu, mt[rg], 1));
            mt[rg] = fmaxf(mt[rg], __shfl_xor_sync(0xffffffffu, mt[rg], 2));
        }

        float mn[4], corr[4];
        #pragma unroll
        for (int rg = 0; rg < 4; rg++) {
            mn[rg]   = fmaxf(m[rg], mt[rg]);
            corr[rg] = exp2f((m[rg] - mn[rg]) * LOG2E);
        }

        float rs[4] = {0.f, 0.f, 0.f, 0.f};
        #pragma unroll
        for (int nc = 0; nc < 8; nc++) {
            s0[nc][0] = exp2f((s0[nc][0] - mn[0]) * LOG2E);
            s0[nc][1] = exp2f((s0[nc][1] - mn[0]) * LOG2E);
            s0[nc][2] = exp2f((s0[nc][2] - mn[1]) * LOG2E);
            s0[nc][3] = exp2f((s0[nc][3] - mn[1]) * LOG2E);
            s1[nc][0] = exp2f((s1[nc][0] - mn[2]) * LOG2E);
            s1[nc][1] = exp2f((s1[nc][1] - mn[2]) * LOG2E);
            s1[nc][2] = exp2f((s1[nc][2] - mn[3]) * LOG2E);
            s1[nc][3] = exp2f((s1[nc][3] - mn[3]) * LOG2E);
            rs[0] += s0[nc][0] + s0[nc][1];
            rs[1] += s0[nc][2] + s0[nc][3];
            rs[2] += s1[nc][0] + s1[nc][1];
            rs[3] += s1[nc][2] + s1[nc][3];
        }
        #pragma unroll
        for (int rg = 0; rg < 4; rg++) {
            rs[rg] += __shfl_xor_sync(0xffffffffu, rs[rg], 1);
            rs[rg] += __shfl_xor_sync(0xffffffffu, rs[rg], 2);
            l[rg] = l[rg] * corr[rg] + rs[rg];
            m[rg] = mn[rg];
        }

        #pragma unroll
        for (int nc = 0; nc < 8; nc++) {
            o0[nc][0] *= corr[0]; o0[nc][1] *= corr[0];
            o0[nc][2] *= corr[1]; o0[nc][3] *= corr[1];
            o1[nc][0] *= corr[2]; o1[nc][1] *= corr[2];
            o1[nc][2] *= corr[3]; o1[nc][3] *= corr[3];
        }

        // O += P V : P C-frag pairs == fp16 A-frag pairs (no shuffles)
        #pragma unroll
        for (int kc = 0; kc < 4; kc++) {
            unsigned pa0[4], pa1[4];
            pa0[0] = pack_h2(s0[2 * kc][0],     s0[2 * kc][1]);
            pa0[1] = pack_h2(s0[2 * kc][2],     s0[2 * kc][3]);
            pa0[2] = pack_h2(s0[2 * kc + 1][0], s0[2 * kc + 1][1]);
            pa0[3] = pack_h2(s0[2 * kc + 1][2], s0[2 * kc + 1][3]);
            pa1[0] = pack_h2(s1[2 * kc][0],     s1[2 * kc][1]);
            pa1[1] = pack_h2(s1[2 * kc][2],     s1[2 * kc][3]);
            pa1[2] = pack_h2(s1[2 * kc + 1][0], s1[2 * kc + 1][1]);
            pa1[3] = pack_h2(s1[2 * kc + 1][2], s1[2 * kc + 1][3]);
            #pragma unroll
            for (int nc = 0; nc < 8; nc++) {
                unsigned b0 = Vsb[(nc * 8 + g) * VT_STRIDE + kc * 8 + t];
                unsigned b1 = Vsb[(nc * 8 + g) * VT_STRIDE + kc * 8 + t + 4];
                mma_f16(o0[nc], pa0, b0, b1);
                mma_f16(o1[nc], pa1, b0, b1);
            }
        }

        __syncthreads();
    }

    // Store unnormalized partials + (m, l)
    float* base = g_Os + (size_t)split * R_TOT * HEAD + rowbase * HEAD;
    #pragma unroll
    for (int nc = 0; nc < 8; nc++) {
        int col = nc * 8 + 2 * t;
        *(float2*)(base + (size_t)(rl0     ) * HEAD + col) = make_float2(o0[nc][0], o0[nc][1]);
        *(float2*)(base + (size_t)(rl0 +  8) * HEAD + col) = make_float2(o0[nc][2], o0[nc][3]);
        *(float2*)(base + (size_t)(rl0 + 16) * HEAD + col) = make_float2(o1[nc][0], o1[nc][1]);
        *(float2*)(base + (size_t)(rl0 + 24) * HEAD + col) = make_float2(o1[nc][2], o1[nc][3]);
    }
    if (t == 0) {
        int pb = split * R_TOT;
        #pragma unroll
        for (int rg = 0; rg < 4; rg++) {
            g_m[pb + rowbase + rl0 + rg * 8] = m[rg];
            g_l[pb + rowbase + rl0 + rg * 8] = l[rg];
        }
    }
}

// ---------------------------------------------------------------------------
// Split-KV combine: one thread per (row, 16-col quarter).
// ---------------------------------------------------------------------------
__global__ void __launch_bounds__(128) combine_kernel(float* __restrict__ out) {
    int gt  = blockIdx.x * 128 + threadIdx.x;
    int row = gt >> 2;
    int qp  = gt & 3;

    float m[SPLIT], l[SPLIT];
    float M = -1e30f;
    #pragma unroll
    for (int s = 0; s < SPLIT; s++) {
        m[s] = g_m[s * R_TOT + row];
        l[s] = g_l[s * R_TOT + row];
        M = fmaxf(M, m[s]);
    }
    float L = 0.f, w[SPLIT];
    #pragma unroll
    for (int s = 0; s < SPLIT; s++) {
        w[s] = exp2f((m[s] - M) * LOG2E);
        L += l[s] * w[s];
    }
    const float inv = 1.f / L;

    float4 acc[4];
    #pragma unroll
    for (int j = 0; j < 4; j++) acc[j] = make_float4(0.f, 0.f, 0.f, 0.f);
    #pragma unroll
    for (int s = 0; s < SPLIT; s++) {
        if (l[s] > 0.f) {
            const float4* p = (const float4*)(g_Os + (size_t)s * R_TOT * HEAD +
                                              (size_t)row * HEAD + qp * 16);
            #pragma unroll
            for (int j = 0; j < 4; j++) {
                float4 v = p[j];
                acc[j].x += w[s] * v.x; acc[j].y += w[s] * v.y;
                acc[j].z += w[s] * v.z; acc[j].w += w[s] * v.w;
            }
        }
    }
    float4* po = (float4*)(out + (size_t)row * HEAD + qp * 16);
    #pragma unroll
    for (int j = 0; j < 4; j++) {
        float4 r = acc[j];
        r.x *= inv; r.y *= inv; r.z *= inv; r.w *= inv;
        po[j] = r;
    }
}

// ---------------------------------------------------------------------------
extern "C" void kernel_launch(void* const* d_in, const int* in_sizes, int n_in,
                              void* d_out, int out_size) {
    const float* x  = (const float*)d_in[0];
    const float* Wq = (const float*)d_in[1];
    const float* Wk = (const float*)d_in[2];
    const float* Wv = (const float*)d_in[3];
    float* out = (float*)d_out;

    cudaFuncSetAttribute(proj_fused_kernel,
                         cudaFuncAttributeMaxDynamicSharedMemorySize, PSMEM);
    cudaFuncSetAttribute(attn_mma_kernel,
                         cudaFuncAttributeMaxDynamicSharedMemorySize, ATTN_SMEM);

    theta_kernel<<<1, 32>>>();
    rope_table_kernel<<<(S_LEN * HALF + 255) / 256, 256>>>();
    wfrag_kernel<<<(3 * NK16 * 8 * 32 + 255) / 256, 256>>>(Wq, Wk, Wv);
    proj_fused_kernel<<<R_TOT / 64, 256, PSMEM>>>(x);
    attn_mma_kernel<<<32 * B_SZ * SPLIT, 128, ATTN_SMEM>>>();
    combine_kernel<<<(R_TOT * 4) / 128, 128>>>(out);
}

// round 16
// speedup vs baseline: 1.0652x; 1.0652x over previous
#include <cuda_runtime.h>
#include <cuda_fp16.h>
#include <math.h>
#include <stdint.h>

#define B_SZ    4
#define S_LEN   4096
#define D_MODEL 1024
#define HEAD    64
#define R_TOT   (B_SZ * S_LEN)
#define HALF    (HEAD / 2)
#define LOG2E   1.4426950408889634f
#define SPLIT   4
#define NK16    (D_MODEL / 16)   // 64 k16-slices

// Scratch (allocation-free rule: __device__ globals)
// g_Qh: fp16 rope(Q)*0.125; g_Kh: fp16 rope(K) [row][col];
// g_Vh2: fp16 V transposed kv-pair packed: [batch][d][spair] half2.
__device__ __half  g_Qh[R_TOT * HEAD];
__device__ __half  g_Kh[R_TOT * HEAD];
__device__ __half2 g_Vh2[R_TOT * HEAD / 2];
__device__ float g_sin[S_LEN * HALF];
__device__ float g_cos[S_LEN * HALF];
__device__ float g_theta[HALF];
__device__ float g_Os[(size_t)SPLIT * R_TOT * HEAD];
__device__ float g_m[SPLIT * R_TOT];
__device__ float g_l[SPLIT * R_TOT];
// Precomputed W B-fragments (fp16, m16n8k16): [which][k16][nc][lane] = {b0, b1}
__device__ uint2 g_Wfh[3][NK16][8][32];

// ---------------------------------------------------------------------------
__device__ __forceinline__ void mma_f16(float c[4], const unsigned a[4],
                                        unsigned b0, unsigned b1) {
    asm volatile(
        "mma.sync.aligned.m16n8k16.row.col.f32.f16.f16.f32 "
        "{%0,%1,%2,%3}, {%4,%5,%6,%7}, {%8,%9}, {%0,%1,%2,%3};\n"
        : "+f"(c[0]), "+f"(c[1]), "+f"(c[2]), "+f"(c[3])
        : "r"(a[0]), "r"(a[1]), "r"(a[2]), "r"(a[3]), "r"(b0), "r"(b1));
}

__device__ __forceinline__ unsigned pack_h2(float a, float b) {
    __half2 h = __floats2half2_rn(a, b);
    return *(unsigned*)&h;
}

__device__ __forceinline__ uint32_t smem_u32(const void* p) {
    uint32_t a;
    asm("{ .reg .u64 t; cvta.to.shared.u64 t, %1; cvt.u32.u64 %0, t; }"
        : "=r"(a) : "l"(p));
    return a;
}

__device__ __forceinline__ void cp16(uint32_t dst, const void* src) {
    asm volatile("cp.async.cg.shared.global [%0], [%1], 16;"
                 :: "r"(dst), "l"(src) : "memory");
}
#define CP_COMMIT()  asm volatile("cp.async.commit_group;" ::: "memory")
#define CP_WAIT(n)   asm volatile("cp.async.wait_group %0;" :: "n"(n) : "memory")

// ---------------------------------------------------------------------------
__global__ void theta_kernel() {
    int i = threadIdx.x;
    if (i < HALF) g_theta[i] = (float)pow(10000.0, -(double)i / (double)HALF);
}

// RoPE table: freq = fp32(s * theta_fp32); accurate sin/cos via double range
// reduction + fp32 Taylor on |r|<=pi/4.
__global__ void rope_table_kernel() {
    int idx = blockIdx.x * blockDim.x + threadIdx.x;
    if (idx >= S_LEN * HALF) return;
    int s = idx >> 5;
    int i = idx & (HALF - 1);
    float fr = (float)s * g_theta[i];

    double x  = (double)fr;
    double kd = rint(x * 0.6366197723675814);
    int    k  = (int)kd;
    double r  = fma(-kd, 1.5707963267948966, x);
    r         = fma(-kd, 6.123233995736766e-17, r);
    float rf = (float)r;
    float r2 = rf * rf;
    float sp = rf * (1.f + r2 * (-1.66666667e-1f + r2 * (8.33333310e-3f +
               r2 * (-1.98412698e-4f + r2 * 2.75573140e-6f))));
    float cp = 1.f + r2 * (-0.5f + r2 * (4.16666679e-2f +
               r2 * (-1.38888892e-3f + r2 * 2.47868524e-5f)));
    float sn, cs;
    switch (k & 3) {
        case 0:  sn = sp;  cs = cp;  break;
        case 1:  sn = cp;  cs = -sp; break;
        case 2:  sn = -sp; cs = -cp; break;
        default: sn = -cp; cs = sp;  break;
    }
    g_sin[idx] = sn;
    g_cos[idx] = cs;
}

// ---------------------------------------------------------------------------
// Precompute W B-fragments (fp16) for m16n8k16 projection MMAs.
// ---------------------------------------------------------------------------
__global__ void wfrag_kernel(const float* __restrict__ Wq,
                             const float* __restrict__ Wk,
                             const float* __restrict__ Wv) {
    int tid = blockIdx.x * 256 + threadIdx.x;
    if (tid >= 3 * NK16 * 8 * 32) return;
    int lane  = tid & 31;
    int nc    = (tid >> 5) & 7;
    int ks    = (tid >> 8) & (NK16 - 1);
    int which = tid >> 14;
    const float* W = (which == 0) ? Wq : (which == 1) ? Wk : Wv;
    int g = lane >> 2, t = lane & 3;
    int n = nc * 8 + g;
    int k0 = ks * 16 + 2 * t;
    uint2 v;
    v.x = pack_h2(W[(size_t)(k0    ) * HEAD + n], W[(size_t)(k0 + 1) * HEAD + n]);
    v.y = pack_h2(W[(size_t)(k0 + 8) * HEAD + n], W[(size_t)(k0 + 9) * HEAD + n]);
    g_Wfh[which][ks][nc][lane] = v;
}

// ---------------------------------------------------------------------------
// FUSED QKV projection v3, fp16 m16n8k16, fp32 accum, + RoPE.
// CTA = 128 rows x 64 cols, 512 threads = 16 warps: warp tile 16 rows x 32
// cols (rowgrp = warp>>1, colgrp = warp&1). Accums 3x4x4 = 48 regs/thread ->
// 16 warps/SM. x + W staged in double-buffered smem via cp.async (the staging
// IS the latency hiding — round-15 direct-LDG experiment regressed).
// ---------------------------------------------------------------------------
#define XS_STRIDE 68
#define XS_BYTES   (128 * XS_STRIDE * 4)             // 34816
#define WFH_BYTES  (4 * 8 * 32 * 8)                  // 8192 per which per chunk
#define WQH_STRIDE (NK16 * 8 * 32 * 8)               // 131072 bytes per which
#define FBUF       (XS_BYTES + 3 * WFH_BYTES)        // 59392
#define FSMEM      (2 * FBUF)                        // 118784

__global__ void __launch_bounds__(512, 1) proj_fused_kernel(const float* __restrict__ x) {
    extern __shared__ char psm[];

    const int tid    = threadIdx.x;
    const int warp   = tid >> 5;
    const int lane   = tid & 31;
    const int g      = lane >> 2;
    const int t      = lane & 3;
    const int rowgrp = warp >> 1;            // 0..7
    const int colgrp = warp & 1;             // 0..1
    const int row0   = blockIdx.x * 128;
    const int r0     = rowgrp * 16 + g;      // local rows r0, r0+8 (0..127)

    const uint32_t smb = smem_u32(psm);

    // --- stage chunk c into buffer b: x (4 lines) + 3 W slices (1 line ea) ---
    auto stage = [&](int c, int b) {
        const uint32_t base = smb + b * FBUF;
        const float* xsrc = x + (size_t)row0 * D_MODEL + c * 64;
        #pragma unroll
        for (int j = 0; j < 4; j++) {
            int idx = j * 512 + tid;
            int r = idx >> 4, c4 = idx & 15;
            cp16(base + (r * XS_STRIDE + c4 * 4) * 4,
                 xsrc + (size_t)r * D_MODEL + c4 * 4);
        }
        const char* ws = (const char*)&g_Wfh[0][0][0][0] + (size_t)c * WFH_BYTES;
        #pragma unroll
        for (int wq = 0; wq < 3; wq++) {
            cp16(base + XS_BYTES + wq * WFH_BYTES + tid * 16,
                 ws + (size_t)wq * WQH_STRIDE + tid * 16);
        }
        CP_COMMIT();
    };

    float cacc[3][4][4] = {};

    stage(0, 0);
    for (int c = 0; c < 16; c++) {
        const int bufsel = c & 1;
        if (c < 15) { stage(c + 1, bufsel ^ 1); CP_WAIT(1); }
        else        { CP_WAIT(0); }
        __syncthreads();

        char* bufp = psm + bufsel * FBUF;
        float* xs  = (float*)bufp;

        #pragma unroll
        for (int ks = 0; ks < 4; ks++) {
            const int cb = ks * 16 + 2 * t;
            float2 f0 = *(float2*)&xs[ r0      * XS_STRIDE + cb];
            float2 f1 = *(float2*)&xs[(r0 + 8) * XS_STRIDE + cb];
            float2 f2 = *(float2*)&xs[ r0      * XS_STRIDE + cb + 8];
            float2 f3 = *(float2*)&xs[(r0 + 8) * XS_STRIDE + cb + 8];
            unsigned a[4];
            a[0] = pack_h2(f0.x, f0.y);
            a[1] = pack_h2(f1.x, f1.y);
            a[2] = pack_h2(f2.x, f2.y);
            a[3] = pack_h2(f3.x, f3.y);

            #pragma unroll
            for (int wq = 0; wq < 3; wq++) {
                const uint2* wrow = (const uint2*)(bufp + XS_BYTES + wq * WFH_BYTES) +
                                    ks * 256 + colgrp * 128 + lane;
                #pragma unroll
                for (int nc = 0; nc < 4; nc++) {
                    uint2 b = wrow[nc * 32];
                    mma_f16(cacc[wq][nc], a, b.x, b.y);
                }
            }
        }
        __syncthreads();
    }

    // Epilogue: RoPE; Q/K -> fp16 direct; V -> smem transpose (pairs along kv)
    const int gr0 = row0 + r0;
    const int s0  = gr0 & (S_LEN - 1);
    const int s1  = (gr0 + 8) & (S_LEN - 1);
    __half* Vt = (__half*)psm;                      // [64 d][136 halfs]
    #pragma unroll
    for (int wq = 0; wq < 3; wq++) {
        float (*cc)[4] = cacc[wq];
        #pragma unroll
        for (int nc = 0; nc < 4; nc++) {
            int col = colgrp * 32 + nc * 8 + 2 * t;
            float v0 = cc[nc][0], v1 = cc[nc][1], v2 = cc[nc][2], v3 = cc[nc][3];
            if (wq < 2) {
                int i0 = col >> 1;
                float sn0 = g_sin[s0 * HALF + i0], cs0 = g_cos[s0 * HALF + i0];
                float sn1 = g_sin[s1 * HALF + i0], cs1 = g_cos[s1 * HALF + i0];
                float a0 = v0 * cs0 - v1 * sn0, b0 = v1 * cs0 + v0 * sn0;
                float a1 = v2 * cs1 - v3 * sn1, b1 = v3 * cs1 + v2 * sn1;
                if (wq == 0) { a0 *= 0.125f; b0 *= 0.125f; a1 *= 0.125f; b1 *= 0.125f; }
                __half* outp = (wq == 0) ? g_Qh : g_Kh;
                *(__half2*)(outp + (size_t)gr0 * HEAD + col)       = __floats2half2_rn(a0, b0);
                *(__half2*)(outp + (size_t)(gr0 + 8) * HEAD + col) = __floats2half2_rn(a1, b1);
            } else {
                Vt[(col    ) * 136 + r0]     = __float2half_rn(v0);
                Vt[(col + 1) * 136 + r0]     = __float2half_rn(v1);
                Vt[(col    ) * 136 + r0 + 8] = __float2half_rn(v2);
                Vt[(col + 1) * 136 + r0 + 8] = __float2half_rn(v3);
            }
        }
    }
    __syncthreads();
    // Cooperative coalesced write of transposed V: 64 d-rows x 64 spairs
    // (= 256 B = 16 uint4 per d-row; 1024 uint4 total)
    {
        const int batch  = row0 >> 12;
        const int spair0 = (row0 & (S_LEN - 1)) >> 1;
        #pragma unroll
        for (int j = 0; j < 2; j++) {
            int idx = j * 512 + tid;
            int d   = idx >> 4;        // 0..63
            int r16 = idx & 15;        // 16 x 16B per 256-byte d-row
            uint4 v = *(uint4*)(psm + d * 272 + r16 * 16);
            *(uint4*)&g_Vh2[(size_t)(batch * HEAD + d) * (S_LEN / 2) + spair0 + r16 * 4] = v;
        }
    }
}

// ---------------------------------------------------------------------------
// fp16 flash attention: m16n8k16 QK and PV, 32 q-rows/warp, 128 q-rows/block,
// 4-way split-KV, cp.async double-buffered. PV A-fragments come straight from
// softmax C-fragments (pair layouts match) — no shuffles.
// ---------------------------------------------------------------------------
#define KT_STRIDE 72                     // halfs per K row
#define KT_BYTES  (64 * KT_STRIDE * 2)   // 9216
#define VT_STRIDE 36                     // half2 per V d-row (d-major)
#define VT_BYTES  (64 * VT_STRIDE * 4)   // 9216
#define KV_BUF2   (KT_BYTES + VT_BYTES)  // 18432
#define ATTN_SMEM (2 * KV_BUF2)          // 36864

__global__ void __launch_bounds__(128, 2) attn_mma_kernel() {
    extern __shared__ char asmem[];

    const int tid   = threadIdx.x;
    const int warp  = tid >> 5;
    const int lane  = tid & 31;
    const int g     = lane >> 2;
    const int t     = lane & 3;
    const int idx   = blockIdx.x;
    const int qt    = 31 - (idx >> 4);
    const int rem   = idx & 15;
    const int batch = rem >> 2;
    const int split = rem & 3;
    const int q0    = qt * 128;
    const int n     = 2 * qt + 2;
    const int lo    = (split * n) >> 2;
    const int hi    = ((split + 1) * n) >> 2;

    const int    rl0     = warp * 32 + g;
    const size_t rowbase = (size_t)batch * S_LEN + q0;

    if (lo == hi) {
        if (t == 0) {
            int pb = split * R_TOT;
            #pragma unroll
            for (int rg = 0; rg < 4; rg++) {
                g_m[pb + rowbase + rl0 + rg * 8] = -1e30f;
                g_l[pb + rowbase + rl0 + rg * 8] = 0.f;
            }
        }
        return;
    }

    const uint32_t smb = smem_u32(asmem);

    // Q tile (128 rows fp16) -> smem [r][72] -> A-frags (pairs along d)
    unsigned qa[2][4][4];
    {
        const __half* Qg = g_Qh + rowbase * HEAD;
        #pragma unroll
        for (int j = 0; j < 8; j++) {
            int i = j * 128 + tid;
            int r = i >> 3, c8 = i & 7;
            cp16(smb + r * (KT_STRIDE * 2) + c8 * 16, Qg + (size_t)r * HEAD + c8 * 8);
        }
        CP_COMMIT(); CP_WAIT(0);
        __syncthreads();
        const __half* Qs = (const __half*)asmem;
        #pragma unroll
        for (int tt = 0; tt < 2; tt++) {
            const int r0 = rl0 + tt * 16;
            #pragma unroll
            for (int kc = 0; kc < 4; kc++) {
                qa[tt][kc][0] = *(const unsigned*)&Qs[ r0      * KT_STRIDE + kc * 16 + 2 * t];
                qa[tt][kc][1] = *(const unsigned*)&Qs[(r0 + 8) * KT_STRIDE + kc * 16 + 2 * t];
                qa[tt][kc][2] = *(const unsigned*)&Qs[ r0      * KT_STRIDE + kc * 16 + 2 * t + 8];
                qa[tt][kc][3] = *(const unsigned*)&Qs[(r0 + 8) * KT_STRIDE + kc * 16 + 2 * t + 8];
            }
        }
        __syncthreads();
    }

    float o0[8][4], o1[8][4];
    #pragma unroll
    for (int nc = 0; nc < 8; nc++) {
        o0[nc][0] = o0[nc][1] = o0[nc][2] = o0[nc][3] = 0.f;
        o1[nc][0] = o1[nc][1] = o1[nc][2] = o1[nc][3] = 0.f;
    }
    float m[4] = {-1e30f, -1e30f, -1e30f, -1e30f};
    float l[4] = {0.f, 0.f, 0.f, 0.f};

    auto stageKV = [&](int jt, int b) {
        const uint32_t kb = smb + b * KV_BUF2;
        const __half*  Kg = g_Kh + ((size_t)batch * S_LEN + jt * 64) * HEAD;
        const __half2* Vg = g_Vh2 + (size_t)batch * HEAD * (S_LEN / 2) + jt * 32;
        #pragma unroll
        for (int j = 0; j < 4; j++) {
            int i = j * 128 + tid;
            int r = i >> 3, c8 = i & 7;
            cp16(kb + r * (KT_STRIDE * 2) + c8 * 16, Kg + (size_t)r * HEAD + c8 * 8);
        }
        // V tile: 64 d-rows x 32 half2 (128 B) = 512 cp16
        #pragma unroll
        for (int j = 0; j < 4; j++) {
            int i = j * 128 + tid;
            int d = i >> 3, c16 = i & 7;
            cp16(kb + KT_BYTES + d * (VT_STRIDE * 4) + c16 * 16,
                 Vg + (size_t)d * (S_LEN / 2) + c16 * 4);
        }
        CP_COMMIT();
    };

    stageKV(lo, 0);
    for (int jt = lo; jt < hi; jt++) {
        const int buf = (jt - lo) & 1;
        if (jt + 1 < hi) { stageKV(jt + 1, buf ^ 1); CP_WAIT(1); }
        else             { CP_WAIT(0); }
        __syncthreads();

        const __half*   Ksb = (const __half*)(asmem + buf * KV_BUF2);
        const unsigned* Vsb = (const unsigned*)(asmem + buf * KV_BUF2 + KT_BYTES);

        // S = Q K^T (fp16, k16) — both A-tiles share each B-fragment
        float s0[8][4], s1[8][4];
        #pragma unroll
        for (int nc = 0; nc < 8; nc++) {
            s0[nc][0] = s0[nc][1] = s0[nc][2] = s0[nc][3] = 0.f;
            s1[nc][0] = s1[nc][1] = s1[nc][2] = s1[nc][3] = 0.f;
            const __half* Krow = Ksb + (nc * 8 + g) * KT_STRIDE;
            #pragma unroll
            for (int kc = 0; kc < 4; kc++) {
                unsigned b0 = *(const unsigned*)&Krow[kc * 16 + 2 * t];
                unsigned b1 = *(const unsigned*)&Krow[kc * 16 + 2 * t + 8];
                mma_f16(s0[nc], qa[0][kc], b0, b1);
                mma_f16(s1[nc], qa[1][kc], b0, b1);
            }
        }

        // Causal mask (last two kv tiles of the 128-row q-tile)
        if (jt >= 2 * qt) {
            const int base = q0 - jt * 64;
            #pragma unroll
            for (int nc = 0; nc < 8; nc++) {
                int cl = nc * 8 + 2 * t;
                int L0 = base + rl0, L1 = L0 + 8, L2 = L0 + 16, L3 = L0 + 24;
                if (cl     > L0) s0[nc][0] = -1e30f;
                if (cl + 1 > L0) s0[nc][1] = -1e30f;
                if (cl     > L1) s0[nc][2] = -1e30f;
                if (cl + 1 > L1) s0[nc][3] = -1e30f;
                if (cl     > L2) s1[nc][0] = -1e30f;
                if (cl + 1 > L2) s1[nc][1] = -1e30f;
                if (cl     > L3) s1[nc][2] = -1e30f;
                if (cl + 1 > L3) s1[nc][3] = -1e30f;
            }
        }

        // Row max per group
        float mt[4] = {-1e30f, -1e30f, -1e30f, -1e30f};
        #pragma unroll
        for (int nc = 0; nc < 8; nc++) {
            mt[0] = fmaxf(mt[0], fmaxf(s0[nc][0], s0[nc][1]));
            mt[1] = fmaxf(mt[1], fmaxf(s0[nc][2], s0[nc][3]));
            mt[2] = fmaxf(mt[2], fmaxf(s1[nc][0], s1[nc][1]));
            mt[3] = fmaxf(mt[3], fmaxf(s1[nc][2], s1[nc][3]));
        }
        #pragma unroll
        for (int rg = 0; rg < 4; rg++) {
            mt[rg] = fmaxf(mt[rg], __shfl_xor_sync(0xffffffffu, mt[rg], 1));
            mt[rg] = fmaxf(mt[rg], __shfl_xor_sync(0xffffffffu, mt[rg], 2));
        }

        float mn[4], corr[4];
        #pragma unroll
        for (int rg = 0; rg < 4; rg++) {
            mn[rg]   = fmaxf(m[rg], mt[rg]);
            corr[rg] = exp2f((m[rg] - mn[rg]) * LOG2E);
        }

        float rs[4] = {0.f, 0.f, 0.f, 0.f};
        #pragma unroll
        for (int nc = 0; nc < 8; nc++) {
            s0[nc][0] = exp2f((s0[nc][0] - mn[0]) * LOG2E);
            s0[nc][1] = exp2f((s0[nc][1] - mn[0]) * LOG2E);
            s0[nc][2] = exp2f((s0[nc][2] - mn[1]) * LOG2E);
            s0[nc][3] = exp2f((s0[nc][3] - mn[1]) * LOG2E);
            s1[nc][0] = exp2f((s1[nc][0] - mn[2]) * LOG2E);
            s1[nc][1] = exp2f((s1[nc][1] - mn[2]) * LOG2E);
            s1[nc][2] = exp2f((s1[nc][2] - mn[3]) * LOG2E);
            s1[nc][3] = exp2f((s1[nc][3] - mn[3]) * LOG2E);
            rs[0] += s0[nc][0] + s0[nc][1];
            rs[1] += s0[nc][2] + s0[nc][3];
            rs[2] += s1[nc][0] + s1[nc][1];
            rs[3] += s1[nc][2] + s1[nc][3];
        }
        #pragma unroll
        for (int rg = 0; rg < 4; rg++) {
            rs[rg] += __shfl_xor_sync(0xffffffffu, rs[rg], 1);
            rs[rg] += __shfl_xor_sync(0xffffffffu, rs[rg], 2);
            l[rg] = l[rg] * corr[rg] + rs[rg];
            m[rg] = mn[rg];
        }

        #pragma unroll
        for (int nc = 0; nc < 8; nc++) {
            o0[nc][0] *= corr[0]; o0[nc][1] *= corr[0];
            o0[nc][2] *= corr[1]; o0[nc][3] *= corr[1];
            o1[nc][0] *= corr[2]; o1[nc][1] *= corr[2];
            o1[nc][2] *= corr[3]; o1[nc][3] *= corr[3];
        }

        // O += P V : P C-frag pairs == fp16 A-frag pairs (no shuffles)
        #pragma unroll
        for (int kc = 0; kc < 4; kc++) {
            unsigned pa0[4], pa1[4];
            pa0[0] = pack_h2(s0[2 * kc][0],     s0[2 * kc][1]);
            pa0[1] = pack_h2(s0[2 * kc][2],     s0[2 * kc][3]);
            pa0[2] = pack_h2(s0[2 * kc + 1][0], s0[2 * kc + 1][1]);
            pa0[3] = pack_h2(s0[2 * kc + 1][2], s0[2 * kc + 1][3]);
            pa1[0] = pack_h2(s1[2 * kc][0],     s1[2 * kc][1]);
            pa1[1] = pack_h2(s1[2 * kc][2],     s1[2 * kc][3]);
            pa1[2] = pack_h2(s1[2 * kc + 1][0], s1[2 * kc + 1][1]);
            pa1[3] = pack_h2(s1[2 * kc + 1][2], s1[2 * kc + 1][3]);
            #pragma unroll
            for (int nc = 0; nc < 8; nc++) {
                unsigned b0 = Vsb[(nc * 8 + g) * VT_STRIDE + kc * 8 + t];
                unsigned b1 = Vsb[(nc * 8 + g) * VT_STRIDE + kc * 8 + t + 4];
                mma_f16(o0[nc], pa0, b0, b1);
                mma_f16(o1[nc], pa1, b0, b1);
            }
        }

        __syncthreads();
    }

    // Store unnormalized partials + (m, l)
    float* base = g_Os + (size_t)split * R_TOT * HEAD + rowbase * HEAD;
    #pragma unroll
    for (int nc = 0; nc < 8; nc++) {
        int col = nc * 8 + 2 * t;
        *(float2*)(base + (size_t)(rl0     ) * HEAD + col) = make_float2(o0[nc][0], o0[nc][1]);
        *(float2*)(base + (size_t)(rl0 +  8) * HEAD + col) = make_float2(o0[nc][2], o0[nc][3]);
        *(float2*)(base + (size_t)(rl0 + 16) * HEAD + col) = make_float2(o1[nc][0], o1[nc][1]);
        *(float2*)(base + (size_t)(rl0 + 24) * HEAD + col) = make_float2(o1[nc][2], o1[nc][3]);
    }
    if (t == 0) {
        int pb = split * R_TOT;
        #pragma unroll
        for (int rg = 0; rg < 4; rg++) {
            g_m[pb + rowbase + rl0 + rg * 8] = m[rg];
            g_l[pb + rowbase + rl0 + rg * 8] = l[rg];
        }
    }
}

// ---------------------------------------------------------------------------
// Split-KV combine: one thread per (row, 16-col quarter).
// ---------------------------------------------------------------------------
__global__ void __launch_bounds__(128) combine_kernel(float* __restrict__ out) {
    int gt  = blockIdx.x * 128 + threadIdx.x;
    int row = gt >> 2;
    int qp  = gt & 3;

    float m[SPLIT], l[SPLIT];
    float M = -1e30f;
    #pragma unroll
    for (int s = 0; s < SPLIT; s++) {
        m[s] = g_m[s * R_TOT + row];
        l[s] = g_l[s * R_TOT + row];
        M = fmaxf(M, m[s]);
    }
    float L = 0.f, w[SPLIT];
    #pragma unroll
    for (int s = 0; s < SPLIT; s++) {
        w[s] = exp2f((m[s] - M) * LOG2E);
        L += l[s] * w[s];
    }
    const float inv = 1.f / L;

    float4 acc[4];
    #pragma unroll
    for (int j = 0; j < 4; j++) acc[j] = make_float4(0.f, 0.f, 0.f, 0.f);
    #pragma unroll
    for (int s = 0; s < SPLIT; s++) {
        if (l[s] > 0.f) {
            const float4* p = (const float4*)(g_Os + (size_t)s * R_TOT * HEAD +
                                              (size_t)row * HEAD + qp * 16);
            #pragma unroll
            for (int j = 0; j < 4; j++) {
                float4 v = p[j];
                acc[j].x += w[s] * v.x; acc[j].y += w[s] * v.y;
                acc[j].z += w[s] * v.z; acc[j].w += w[s] * v.w;
            }
        }
    }
    float4* po = (float4*)(out + (size_t)row * HEAD + qp * 16);
    #pragma unroll
    for (int j = 0; j < 4; j++) {
        float4 r = acc[j];
        r.x *= inv; r.y *= inv; r.z *= inv; r.w *= inv;
        po[j] = r;
    }
}

// ---------------------------------------------------------------------------
extern "C" void kernel_launch(void* const* d_in, const int* in_sizes, int n_in,
                              void* d_out, int out_size) {
    const float* x  = (const float*)d_in[0];
    const float* Wq = (const float*)d_in[1];
    const float* Wk = (const float*)d_in[2];
    const float* Wv = (const float*)d_in[3];
    float* out = (float*)d_out;

    cudaFuncSetAttribute(proj_fused_kernel,
                         cudaFuncAttributeMaxDynamicSharedMemorySize, FSMEM);
    cudaFuncSetAttribute(attn_mma_kernel,
                         cudaFuncAttributeMaxDynamicSharedMemorySize, ATTN_SMEM);

    theta_kernel<<<1, 32>>>();
    rope_table_kernel<<<(S_LEN * HALF + 255) / 256, 256>>>();
    wfrag_kernel<<<(3 * NK16 * 8 * 32 + 255) / 256, 256>>>(Wq, Wk, Wv);
    proj_fused_kernel<<<R_TOT / 128, 512, FSMEM>>>(x);
    attn_mma_kernel<<<32 * B_SZ * SPLIT, 128, ATTN_SMEM>>>();
    combine_kernel<<<(R_TOT * 4) / 128, 128>>>(out);
}

// round 17
// speedup vs baseline: 1.1225x; 1.0538x over previous
#include <cuda_runtime.h>
#include <cuda_fp16.h>
#include <math.h>
#include <stdint.h>

#define B_SZ    4
#define S_LEN   4096
#define D_MODEL 1024
#define HEAD    64
#define R_TOT   (B_SZ * S_LEN)
#define HALF    (HEAD / 2)
#define LOG2E   1.4426950408889634f
#define SPLIT   4
#define NK16    (D_MODEL / 16)   // 64 k16-slices

// Scratch (allocation-free rule: __device__ globals)
// g_Qh: fp16 rope(Q)*0.125; g_Kh: fp16 rope(K) [row][col];
// g_Vh2: fp16 V transposed kv-pair packed: [batch][d][spair] half2.
__device__ __half  g_Qh[R_TOT * HEAD];
__device__ __half  g_Kh[R_TOT * HEAD];
__device__ __half2 g_Vh2[R_TOT * HEAD / 2];
__device__ float g_sin[S_LEN * HALF];
__device__ float g_cos[S_LEN * HALF];
__device__ float g_theta[HALF];
__device__ float g_Os[(size_t)SPLIT * R_TOT * HEAD];
__device__ float g_m[SPLIT * R_TOT];
__device__ float g_l[SPLIT * R_TOT];
// Precomputed W B-fragments (fp16, m16n8k16): [which][k16][nc][lane] = {b0, b1}
__device__ uint2 g_Wfh[3][NK16][8][32];

// ---------------------------------------------------------------------------
__device__ __forceinline__ void mma_f16(float c[4], const unsigned a[4],
                                        unsigned b0, unsigned b1) {
    asm volatile(
        "mma.sync.aligned.m16n8k16.row.col.f32.f16.f16.f32 "
        "{%0,%1,%2,%3}, {%4,%5,%6,%7}, {%8,%9}, {%0,%1,%2,%3};\n"
        : "+f"(c[0]), "+f"(c[1]), "+f"(c[2]), "+f"(c[3])
        : "r"(a[0]), "r"(a[1]), "r"(a[2]), "r"(a[3]), "r"(b0), "r"(b1));
}

__device__ __forceinline__ unsigned pack_h2(float a, float b) {
    __half2 h = __floats2half2_rn(a, b);
    return *(unsigned*)&h;
}

__device__ __forceinline__ uint32_t smem_u32(const void* p) {
    uint32_t a;
    asm("{ .reg .u64 t; cvta.to.shared.u64 t, %1; cvt.u32.u64 %0, t; }"
        : "=r"(a) : "l"(p));
    return a;
}

__device__ __forceinline__ void cp16(uint32_t dst, const void* src) {
    asm volatile("cp.async.cg.shared.global [%0], [%1], 16;"
                 :: "r"(dst), "l"(src) : "memory");
}
#define CP_COMMIT()  asm volatile("cp.async.commit_group;" ::: "memory")
#define CP_WAIT(n)   asm volatile("cp.async.wait_group %0;" :: "n"(n) : "memory")

// ---------------------------------------------------------------------------
__global__ void theta_kernel() {
    int i = threadIdx.x;
    if (i < HALF) g_theta[i] = (float)pow(10000.0, -(double)i / (double)HALF);
}

// RoPE table: freq = fp32(s * theta_fp32); accurate sin/cos via double range
// reduction + fp32 Taylor on |r|<=pi/4.
__global__ void rope_table_kernel() {
    int idx = blockIdx.x * blockDim.x + threadIdx.x;
    if (idx >= S_LEN * HALF) return;
    int s = idx >> 5;
    int i = idx & (HALF - 1);
    float fr = (float)s * g_theta[i];

    double x  = (double)fr;
    double kd = rint(x * 0.6366197723675814);
    int    k  = (int)kd;
    double r  = fma(-kd, 1.5707963267948966, x);
    r         = fma(-kd, 6.123233995736766e-17, r);
    float rf = (float)r;
    float r2 = rf * rf;
    float sp = rf * (1.f + r2 * (-1.66666667e-1f + r2 * (8.33333310e-3f +
               r2 * (-1.98412698e-4f + r2 * 2.75573140e-6f))));
    float cp = 1.f + r2 * (-0.5f + r2 * (4.16666679e-2f +
               r2 * (-1.38888892e-3f + r2 * 2.47868524e-5f)));
    float sn, cs;
    switch (k & 3) {
        case 0:  sn = sp;  cs = cp;  break;
        case 1:  sn = cp;  cs = -sp; break;
        case 2:  sn = -sp; cs = -cp; break;
        default: sn = -cp; cs = sp;  break;
    }
    g_sin[idx] = sn;
    g_cos[idx] = cs;
}

// ---------------------------------------------------------------------------
// Precompute W B-fragments (fp16) for m16n8k16 projection MMAs.
// ---------------------------------------------------------------------------
__global__ void wfrag_kernel(const float* __restrict__ Wq,
                             const float* __restrict__ Wk,
                             const float* __restrict__ Wv) {
    int tid = blockIdx.x * 256 + threadIdx.x;
    if (tid >= 3 * NK16 * 8 * 32) return;
    int lane  = tid & 31;
    int nc    = (tid >> 5) & 7;
    int ks    = (tid >> 8) & (NK16 - 1);
    int which = tid >> 14;
    const float* W = (which == 0) ? Wq : (which == 1) ? Wk : Wv;
    int g = lane >> 2, t = lane & 3;
    int n = nc * 8 + g;
    int k0 = ks * 16 + 2 * t;
    uint2 v;
    v.x = pack_h2(W[(size_t)(k0    ) * HEAD + n], W[(size_t)(k0 + 1) * HEAD + n]);
    v.y = pack_h2(W[(size_t)(k0 + 8) * HEAD + n], W[(size_t)(k0 + 9) * HEAD + n]);
    g_Wfh[which][ks][nc][lane] = v;
}

// ---------------------------------------------------------------------------
// FUSED QKV projection (round-13 shape: 256 thr, 8 warps x 16 rows x 64 cols,
// 96 accums) with a THREE-stage cp.async ring: prefetch depth 2 chunks keeps
// ~34 KB of x in flight per SM to cover DRAM latency (the round-13 double
// buffer measured only 1.9 TB/s achieved BW — outstanding-bytes limited).
// Epilogue: Q/K -> fp16 (Q prescaled 0.125); V -> transposed fp16 kv-pairs.
// ---------------------------------------------------------------------------
#define XS_STRIDE 68
#define XS_BYTES   (128 * XS_STRIDE * 4)             // 34816
#define WFH_BYTES  (4 * 8 * 32 * 8)                  // 8192 per which per chunk
#define WQH_STRIDE (NK16 * 8 * 32 * 8)               // 131072 bytes per which
#define FBUF       (XS_BYTES + 3 * WFH_BYTES)        // 59392
#define NSTAGE     3
#define FSMEM      (NSTAGE * FBUF)                   // 178176

__global__ void __launch_bounds__(256, 1) proj_fused_kernel(const float* __restrict__ x) {
    extern __shared__ char psm[];

    const int tid  = threadIdx.x;
    const int warp = tid >> 5;
    const int lane = tid & 31;
    const int g    = lane >> 2;
    const int t    = lane & 3;
    const int row0 = blockIdx.x * 128;
    const int r0   = warp * 16 + g;      // local row; rows r0, r0+8

    const uint32_t smb = smem_u32(psm);

    auto stage = [&](int c, int b) {
        const uint32_t base = smb + b * FBUF;
        const float* xsrc = x + (size_t)row0 * D_MODEL + c * 64;
        #pragma unroll
        for (int j = 0; j < 8; j++) {
            int idx = j * 256 + tid;
            int r = idx >> 4, c4 = idx & 15;
            cp16(base + (r * XS_STRIDE + c4 * 4) * 4,
                 xsrc + (size_t)r * D_MODEL + c4 * 4);
        }
        const char* ws = (const char*)&g_Wfh[0][0][0][0] + (size_t)c * WFH_BYTES;
        #pragma unroll
        for (int wq = 0; wq < 3; wq++) {
            #pragma unroll
            for (int j = 0; j < 2; j++) {
                int idx = j * 256 + tid;
                cp16(base + XS_BYTES + wq * WFH_BYTES + idx * 16,
                     ws + (size_t)wq * WQH_STRIDE + idx * 16);
            }
        }
        CP_COMMIT();
    };

    float cacc[3][8][4] = {};

    stage(0, 0);
    stage(1, 1);
    for (int c = 0; c < 16; c++) {
        if (c + 2 < 16) stage(c + 2, (c + 2) % NSTAGE);
        if (c <= 13)      { CP_WAIT(2); }
        else if (c == 14) { CP_WAIT(1); }
        else              { CP_WAIT(0); }
        __syncthreads();

        char* bufp = psm + (c % NSTAGE) * FBUF;
        float* xs  = (float*)bufp;

        #pragma unroll
        for (int ks = 0; ks < 4; ks++) {
            const int cb = ks * 16 + 2 * t;
            float2 f0 = *(float2*)&xs[ r0      * XS_STRIDE + cb];
            float2 f1 = *(float2*)&xs[(r0 + 8) * XS_STRIDE + cb];
            float2 f2 = *(float2*)&xs[ r0      * XS_STRIDE + cb + 8];
            float2 f3 = *(float2*)&xs[(r0 + 8) * XS_STRIDE + cb + 8];
            unsigned a[4];
            a[0] = pack_h2(f0.x, f0.y);
            a[1] = pack_h2(f1.x, f1.y);
            a[2] = pack_h2(f2.x, f2.y);
            a[3] = pack_h2(f3.x, f3.y);

            #pragma unroll
            for (int wq = 0; wq < 3; wq++) {
                const uint2* wrow =
                    (const uint2*)(bufp + XS_BYTES + wq * WFH_BYTES) + ks * 256 + lane;
                #pragma unroll
                for (int nc = 0; nc < 8; nc++) {
                    uint2 b = wrow[nc * 32];
                    mma_f16(cacc[wq][nc], a, b.x, b.y);
                }
            }
        }
        __syncthreads();
    }

    // Epilogue: RoPE; Q/K -> fp16 direct; V -> smem transpose (pairs along kv)
    const int gr0 = row0 + r0;
    const int s0  = gr0 & (S_LEN - 1);
    const int s1  = (gr0 + 8) & (S_LEN - 1);
    __half* Vt = (__half*)psm;                      // [64 d][136 halfs]
    #pragma unroll
    for (int wq = 0; wq < 3; wq++) {
        float (*cc)[4] = cacc[wq];
        #pragma unroll
        for (int nc = 0; nc < 8; nc++) {
            int col = nc * 8 + 2 * t;
            float v0 = cc[nc][0], v1 = cc[nc][1], v2 = cc[nc][2], v3 = cc[nc][3];
            if (wq < 2) {
                int i0 = col >> 1;
                float sn0 = g_sin[s0 * HALF + i0], cs0 = g_cos[s0 * HALF + i0];
                float sn1 = g_sin[s1 * HALF + i0], cs1 = g_cos[s1 * HALF + i0];
                float a0 = v0 * cs0 - v1 * sn0, b0 = v1 * cs0 + v0 * sn0;
                float a1 = v2 * cs1 - v3 * sn1, b1 = v3 * cs1 + v2 * sn1;
                if (wq == 0) { a0 *= 0.125f; b0 *= 0.125f; a1 *= 0.125f; b1 *= 0.125f; }
                __half* outp = (wq == 0) ? g_Qh : g_Kh;
                *(__half2*)(outp + (size_t)gr0 * HEAD + col)       = __floats2half2_rn(a0, b0);
                *(__half2*)(outp + (size_t)(gr0 + 8) * HEAD + col) = __floats2half2_rn(a1, b1);
            } else {
                Vt[(col    ) * 136 + r0]     = __float2half_rn(v0);
                Vt[(col + 1) * 136 + r0]     = __float2half_rn(v1);
                Vt[(col    ) * 136 + r0 + 8] = __float2half_rn(v2);
                Vt[(col + 1) * 136 + r0 + 8] = __float2half_rn(v3);
            }
        }
    }
    __syncthreads();
    // Cooperative coalesced write of transposed V: 64 d x 64 spairs
    {
        const int batch  = row0 >> 12;
        const int spair0 = (row0 & (S_LEN - 1)) >> 1;
        #pragma unroll
        for (int j = 0; j < 4; j++) {
            int idx = j * 256 + tid;
            int d   = idx >> 4;
            int r16 = idx & 15;
            uint4 v = *(uint4*)(psm + d * 272 + r16 * 16);
            *(uint4*)&g_Vh2[(size_t)(batch * HEAD + d) * (S_LEN / 2) + spair0 + r16 * 4] = v;
        }
    }
}

// ---------------------------------------------------------------------------
// fp16 flash attention: m16n8k16 QK and PV, 32 q-rows/warp, 128 q-rows/block,
// 4-way split-KV, cp.async double-buffered. PV A-fragments come straight from
// softmax C-fragments (pair layouts match) — no shuffles.
// ---------------------------------------------------------------------------
#define KT_STRIDE 72                     // halfs per K row
#define KT_BYTES  (64 * KT_STRIDE * 2)   // 9216
#define VT_STRIDE 36                     // half2 per V d-row (d-major)
#define VT_BYTES  (64 * VT_STRIDE * 4)   // 9216
#define KV_BUF2   (KT_BYTES + VT_BYTES)  // 18432
#define ATTN_SMEM (2 * KV_BUF2)          // 36864

__global__ void __launch_bounds__(128, 2) attn_mma_kernel() {
    extern __shared__ char asmem[];

    const int tid   = threadIdx.x;
    const int warp  = tid >> 5;
    const int lane  = tid & 31;
    const int g     = lane >> 2;
    const int t     = lane & 3;
    const int idx   = blockIdx.x;
    const int qt    = 31 - (idx >> 4);
    const int rem   = idx & 15;
    const int batch = rem >> 2;
    const int split = rem & 3;
    const int q0    = qt * 128;
    const int n     = 2 * qt + 2;
    const int lo    = (split * n) >> 2;
    const int hi    = ((split + 1) * n) >> 2;

    const int    rl0     = warp * 32 + g;
    const size_t rowbase = (size_t)batch * S_LEN + q0;

    if (lo == hi) {
        if (t == 0) {
            int pb = split * R_TOT;
            #pragma unroll
            for (int rg = 0; rg < 4; rg++) {
                g_m[pb + rowbase + rl0 + rg * 8] = -1e30f;
                g_l[pb + rowbase + rl0 + rg * 8] = 0.f;
            }
        }
        return;
    }

    const uint32_t smb = smem_u32(asmem);

    // Q tile (128 rows fp16) -> smem [r][72] -> A-frags (pairs along d)
    unsigned qa[2][4][4];
    {
        const __half* Qg = g_Qh + rowbase * HEAD;
        #pragma unroll
        for (int j = 0; j < 8; j++) {
            int i = j * 128 + tid;
            int r = i >> 3, c8 = i & 7;
            cp16(smb + r * (KT_STRIDE * 2) + c8 * 16, Qg + (size_t)r * HEAD + c8 * 8);
        }
        CP_COMMIT(); CP_WAIT(0);
        __syncthreads();
        const __half* Qs = (const __half*)asmem;
        #pragma unroll
        for (int tt = 0; tt < 2; tt++) {
            const int r0 = rl0 + tt * 16;
            #pragma unroll
            for (int kc = 0; kc < 4; kc++) {
                qa[tt][kc][0] = *(const unsigned*)&Qs[ r0      * KT_STRIDE + kc * 16 + 2 * t];
                qa[tt][kc][1] = *(const unsigned*)&Qs[(r0 + 8) * KT_STRIDE + kc * 16 + 2 * t];
                qa[tt][kc][2] = *(const unsigned*)&Qs[ r0      * KT_STRIDE + kc * 16 + 2 * t + 8];
                qa[tt][kc][3] = *(const unsigned*)&Qs[(r0 + 8) * KT_STRIDE + kc * 16 + 2 * t + 8];
            }
        }
        __syncthreads();
    }

    float o0[8][4], o1[8][4];
    #pragma unroll
    for (int nc = 0; nc < 8; nc++) {
        o0[nc][0] = o0[nc][1] = o0[nc][2] = o0[nc][3] = 0.f;
        o1[nc][0] = o1[nc][1] = o1[nc][2] = o1[nc][3] = 0.f;
    }
    float m[4] = {-1e30f, -1e30f, -1e30f, -1e30f};
    float l[4] = {0.f, 0.f, 0.f, 0.f};

    auto stageKV = [&](int jt, int b) {
        const uint32_t kb = smb + b * KV_BUF2;
        const __half*  Kg = g_Kh + ((size_t)batch * S_LEN + jt * 64) * HEAD;
        const __half2* Vg = g_Vh2 + (size_t)batch * HEAD * (S_LEN / 2) + jt * 32;
        #pragma unroll
        for (int j = 0; j < 4; j++) {
            int i = j * 128 + tid;
            int r = i >> 3, c8 = i & 7;
            cp16(kb + r * (KT_STRIDE * 2) + c8 * 16, Kg + (size_t)r * HEAD + c8 * 8);
        }
        // V tile: 64 d-rows x 32 half2 (128 B) = 512 cp16
        #pragma unroll
        for (int j = 0; j < 4; j++) {
            int i = j * 128 + tid;
            int d = i >> 3, c16 = i & 7;
            cp16(kb + KT_BYTES + d * (VT_STRIDE * 4) + c16 * 16,
                 Vg + (size_t)d * (S_LEN / 2) + c16 * 4);
        }
        CP_COMMIT();
    };

    stageKV(lo, 0);
    for (int jt = lo; jt < hi; jt++) {
        const int buf = (jt - lo) & 1;
        if (jt + 1 < hi) { stageKV(jt + 1, buf ^ 1); CP_WAIT(1); }
        else             { CP_WAIT(0); }
        __syncthreads();

        const __half*   Ksb = (const __half*)(asmem + buf * KV_BUF2);
        const unsigned* Vsb = (const unsigned*)(asmem + buf * KV_BUF2 + KT_BYTES);

        // S = Q K^T (fp16, k16) — both A-tiles share each B-fragment
        float s0[8][4], s1[8][4];
        #pragma unroll
        for (int nc = 0; nc < 8; nc++) {
            s0[nc][0] = s0[nc][1] = s0[nc][2] = s0[nc][3] = 0.f;
            s1[nc][0] = s1[nc][1] = s1[nc][2] = s1[nc][3] = 0.f;
            const __half* Krow = Ksb + (nc * 8 + g) * KT_STRIDE;
            #pragma unroll
            for (int kc = 0; kc < 4; kc++) {
                unsigned b0 = *(const unsigned*)&Krow[kc * 16 + 2 * t];
                unsigned b1 = *(const unsigned*)&Krow[kc * 16 + 2 * t + 8];
                mma_f16(s0[nc], qa[0][kc], b0, b1);
                mma_f16(s1[nc], qa[1][kc], b0, b1);
            }
        }

        // Causal mask (last two kv tiles of the 128-row q-tile)
        if (jt >= 2 * qt) {
            const int base = q0 - jt * 64;
            #pragma unroll
            for (int nc = 0; nc < 8; nc++) {
                int cl = nc * 8 + 2 * t;
                int L0 = base + rl0, L1 = L0 + 8, L2 = L0 + 16, L3 = L0 + 24;
                if (cl     > L0) s0[nc][0] = -1e30f;
                if (cl + 1 > L0) s0[nc][1] = -1e30f;
                if (cl     > L1) s0[nc][2] = -1e30f;
                if (cl + 1 > L1) s0[nc][3] = -1e30f;
                if (cl     > L2) s1[nc][0] = -1e30f;
                if (cl + 1 > L2) s1[nc][1] = -1e30f;
                if (cl     > L3) s1[nc][2] = -1e30f;
                if (cl + 1 > L3) s1[nc][3] = -1e30f;
            }
        }

        // Row max per group
        float mt[4] = {-1e30f, -1e30f, -1e30f, -1e30f};
        #pragma unroll
        for (int nc = 0; nc < 8; nc++) {
            mt[0] = fmaxf(mt[0], fmaxf(s0[nc][0], s0[nc][1]));
            mt[1] = fmaxf(mt[1], fmaxf(s0[nc][2], s0[nc][3]));
            mt[2] = fmaxf(mt[2], fmaxf(s1[nc][0], s1[nc][1]));
            mt[3] = fmaxf(mt[3], fmaxf(s1[nc][2], s1[nc][3]));
        }
        #pragma unroll
        for (int rg = 0; rg < 4; rg++) {
            mt[rg] = fmaxf(mt[rg], __shfl_xor_sync(0xffffffffu, mt[rg], 1));
            mt[rg] = fmaxf(mt[rg], __shfl_xor_sync(0xffffffffu, mt[rg], 2));
        }

        float mn[4], corr[4];
        #pragma unroll
        for (int rg = 0; rg < 4; rg++) {
            mn[rg]   = fmaxf(m[rg], mt[rg]);
            corr[rg] = exp2f((m[rg] - mn[rg]) * LOG2E);
        }

        float rs[4] = {0.f, 0.f, 0.f, 0.f};
        #pragma unroll
        for (int nc = 0; nc < 8; nc++) {
            s0[nc][0] = exp2f((s0[nc][0] - mn[0]) * LOG2E);
            s0[nc][1] = exp2f((s0[nc][1] - mn[0]) * LOG2E);
            s0[nc][2] = exp2f((s0[nc][2] - mn[1]) * LOG2E);
            s0[nc][3] = exp2f((s0[nc][3] - mn[1]) * LOG2E);
            s1[nc][0] = exp2f((s1[nc][0] - mn[2]) * LOG2E);
            s1[nc][1] = exp2f((s1[nc][1] - mn[2]) * LOG2E);
            s1[nc][2] = exp2f((s1[nc][2] - mn[3]) * LOG2E);
            s1[nc][3] = exp2f((s1[nc][3] - mn[3]) * LOG2E);
            rs[0] += s0[nc][0] + s0[nc][1];
            rs[1] += s0[nc][2] + s0[nc][3];
            rs[2] += s1[nc][0] + s1[nc][1];
            rs[3] += s1[nc][2] + s1[nc][3];
        }
        #pragma unroll
        for (int rg = 0; rg < 4; rg++) {
            rs[rg] += __shfl_xor_sync(0xffffffffu, rs[rg], 1);
            rs[rg] += __shfl_xor_sync(0xffffffffu, rs[rg], 2);
            l[rg] = l[rg] * corr[rg] + rs[rg];
            m[rg] = mn[rg];
        }

        #pragma unroll
        for (int nc = 0; nc < 8; nc++) {
            o0[nc][0] *= corr[0]; o0[nc][1] *= corr[0];
            o0[nc][2] *= corr[1]; o0[nc][3] *= corr[1];
            o1[nc][0] *= corr[2]; o1[nc][1] *= corr[2];
            o1[nc][2] *= corr[3]; o1[nc][3] *= corr[3];
        }

        // O += P V : P C-frag pairs == fp16 A-frag pairs (no shuffles)
        #pragma unroll
        for (int kc = 0; kc < 4; kc++) {
            unsigned pa0[4], pa1[4];
            pa0[0] = pack_h2(s0[2 * kc][0],     s0[2 * kc][1]);
            pa0[1] = pack_h2(s0[2 * kc][2],     s0[2 * kc][3]);
            pa0[2] = pack_h2(s0[2 * kc + 1][0], s0[2 * kc + 1][1]);
            pa0[3] = pack_h2(s0[2 * kc + 1][2], s0[2 * kc + 1][3]);
            pa1[0] = pack_h2(s1[2 * kc][0],     s1[2 * kc][1]);
            pa1[1] = pack_h2(s1[2 * kc][2],     s1[2 * kc][3]);
            pa1[2] = pack_h2(s1[2 * kc + 1][0], s1[2 * kc + 1][1]);
            pa1[3] = pack_h2(s1[2 * kc + 1][2], s1[2 * kc + 1][3]);
            #pragma unroll
            for (int nc = 0; nc < 8; nc++) {
                unsigned b0 = Vsb[(nc * 8 + g) * VT_STRIDE + kc * 8 + t];
                unsigned b1 = Vsb[(nc * 8 + g) * VT_STRIDE + kc * 8 + t + 4];
                mma_f16(o0[nc], pa0, b0, b1);
                mma_f16(o1[nc], pa1, b0, b1);
            }
        }

        __syncthreads();
    }

    // Store unnormalized partials + (m, l)
    float* base = g_Os + (size_t)split * R_TOT * HEAD + rowbase * HEAD;
    #pragma unroll
    for (int nc = 0; nc < 8; nc++) {
        int col = nc * 8 + 2 * t;
        *(float2*)(base + (size_t)(rl0     ) * HEAD + col) = make_float2(o0[nc][0], o0[nc][1]);
        *(float2*)(base + (size_t)(rl0 +  8) * HEAD + col) = make_float2(o0[nc][2], o0[nc][3]);
        *(float2*)(base + (size_t)(rl0 + 16) * HEAD + col) = make_float2(o1[nc][0], o1[nc][1]);
        *(float2*)(base + (size_t)(rl0 + 24) * HEAD + col) = make_float2(o1[nc][2], o1[nc][3]);
    }
    if (t == 0) {
        int pb = split * R_TOT;
        #pragma unroll
        for (int rg = 0; rg < 4; rg++) {
            g_m[pb + rowbase + rl0 + rg * 8] = m[rg];
            g_l[pb + rowbase + rl0 + rg * 8] = l[rg];
        }
    }
}

// ---------------------------------------------------------------------------
// Split-KV combine: one thread per (row, 16-col quarter).
// ---------------------------------------------------------------------------
__global__ void __launch_bounds__(128) combine_kernel(float* __restrict__ out) {
    int gt  = blockIdx.x * 128 + threadIdx.x;
    int row = gt >> 2;
    int qp  = gt & 3;

    float m[SPLIT], l[SPLIT];
    float M = -1e30f;
    #pragma unroll
    for (int s = 0; s < SPLIT; s++) {
        m[s] = g_m[s * R_TOT + row];
        l[s] = g_l[s * R_TOT + row];
        M = fmaxf(M, m[s]);
    }
    float L = 0.f, w[SPLIT];
    #pragma unroll
    for (int s = 0; s < SPLIT; s++) {
        w[s] = exp2f((m[s] - M) * LOG2E);
        L += l[s] * w[s];
    }
    const float inv = 1.f / L;

    float4 acc[4];
    #pragma unroll
    for (int j = 0; j < 4; j++) acc[j] = make_float4(0.f, 0.f, 0.f, 0.f);
    #pragma unroll
    for (int s = 0; s < SPLIT; s++) {
        if (l[s] > 0.f) {
            const float4* p = (const float4*)(g_Os + (size_t)s * R_TOT * HEAD +
                                              (size_t)row * HEAD + qp * 16);
            #pragma unroll
            for (int j = 0; j < 4; j++) {
                float4 v = p[j];
                acc[j].x += w[s] * v.x; acc[j].y += w[s] * v.y;
                acc[j].z += w[s] * v.z; acc[j].w += w[s] * v.w;
            }
        }
    }
    float4* po = (float4*)(out + (size_t)row * HEAD + qp * 16);
    #pragma unroll
    for (int j = 0; j < 4; j++) {
        float4 r = acc[j];
        r.x *= inv; r.y *= inv; r.z *= inv; r.w *= inv;
        po[j] = r;
    }
}

// ---------------------------------------------------------------------------
extern "C" void kernel_launch(void* const* d_in, const int* in_sizes, int n_in,
                              void* d_out, int out_size) {
    const float* x  = (const float*)d_in[0];
    const float* Wq = (const float*)d_in[1];
    const float* Wk = (const float*)d_in[2];
    const float* Wv = (const float*)d_in[3];
    float* out = (float*)d_out;

    cudaFuncSetAttribute(proj_fused_kernel,
                         cudaFuncAttributeMaxDynamicSharedMemorySize, FSMEM);
    cudaFuncSetAttribute(attn_mma_kernel,
                         cudaFuncAttributeMaxDynamicSharedMemorySize, ATTN_SMEM);

    theta_kernel<<<1, 32>>>();
    rope_table_kernel<<<(S_LEN * HALF + 255) / 256, 256>>>();
    wfrag_kernel<<<(3 * NK16 * 8 * 32 + 255) / 256, 256>>>(Wq, Wk, Wv);
    proj_fused_kernel<<<R_TOT / 128, 256, FSMEM>>>(x);
    attn_mma_kernel<<<32 * B_SZ * SPLIT, 128, ATTN_SMEM>>>();
    combine_kernel<<<(R_TOT * 4) / 128, 128>>>(out);
}